// round 3
// baseline (speedup 1.0000x reference)
#include <cuda_runtime.h>

#define IMG   64
#define OUTW  61
#define NB    256
#define NOUT  (OUTW * OUTW)

// Per-image partial sums of sigmoid(conv) — deterministic scratch.
__device__ float g_partials[NB];

__global__ __launch_bounds__(256) void conv_sigmoid_partial(
    const float* __restrict__ data,
    const float* __restrict__ conv_w,
    const float* __restrict__ conv_b)
{
    __shared__ float img[IMG * IMG];   // 16 KB
    __shared__ float w[16];
    __shared__ float red[8];

    const int b = blockIdx.x;
    const int t = threadIdx.x;

    if (t < 16) w[t] = conv_w[t];

    // Coalesced float4 stage of this image (4096 floats = 1024 float4).
    const float4* src = (const float4*)(data + (size_t)b * IMG * IMG);
    float4*       dst = (float4*)img;
    #pragma unroll
    for (int k = 0; k < 4; k++)
        dst[t + k * 256] = src[t + k * 256];
    __syncthreads();

    const float bias = conv_b[0];

    float lsum = 0.0f;
    for (int idx = t; idx < NOUT; idx += 256) {
        const int i = idx / OUTW;
        const int j = idx - i * OUTW;
        float acc = bias;
        #pragma unroll
        for (int di = 0; di < 4; di++) {
            #pragma unroll
            for (int dj = 0; dj < 4; dj++)
                acc = fmaf(img[(i + di) * IMG + (j + dj)], w[di * 4 + dj], acc);
        }
        // sigmoid; __expf is plenty accurate for a 1e-3 tolerance on a mean.
        lsum += 1.0f / (1.0f + __expf(-acc));
    }

    // Warp tree-reduce (deterministic).
    #pragma unroll
    for (int o = 16; o; o >>= 1)
        lsum += __shfl_xor_sync(0xffffffffu, lsum, o);
    if ((t & 31) == 0) red[t >> 5] = lsum;
    __syncthreads();
    if (t == 0) {
        float v = 0.0f;
        #pragma unroll
        for (int k = 0; k < 8; k++) v += red[k];
        g_partials[b] = v;
    }
}

__global__ __launch_bounds__(256) void finalize_kernel(
    const float* __restrict__ data,
    float* __restrict__ out)
{
    __shared__ float red[8];
    const int t = threadIdx.x;

    // Reduce the 256 per-image partials (deterministic tree).
    float v = g_partials[t];
    #pragma unroll
    for (int o = 16; o; o >>= 1)
        v += __shfl_xor_sync(0xffffffffu, v, o);
    if ((t & 31) == 0) red[t >> 5] = v;
    __syncthreads();

    float total = 0.0f;
    #pragma unroll
    for (int k = 0; k < 8; k++) total += red[k];

    const float mean = total * (1.0f / ((float)NB * (float)NOUT));
    const float base = 0.5f * mean;

    // Analytic quantum expectation for batch element t.
    // State stays exactly uniform under RX(theta in {0, pi_f32}) and the CX
    // chain, so qexp = prod_q (c^2 + s^2) - 1 with theta = float32(pi).
    const float th = 0.5f * 3.14159274101257324e+00f;  // float32(pi)/2
    const float c  = cosf(th);
    const float s  = sinf(th);
    const float r  = c * c + s * s;                    // == 1.0f in fp32

    const float* flat = data + (size_t)t * IMG * IMG;
    int k = 0;
    #pragma unroll
    for (int q = 0; q < 16; q++)
        k += (flat[q] > 0.0f) ? 1 : 0;

    // r == 1.0f so this is exactly 0; kept for fidelity to the math.
    float prod = 1.0f;
    for (int q = 0; q < k; q++) prod *= r;
    const float qexp = prod - 1.0f;

    out[t] = base + 0.5f * qexp;
}

extern "C" void kernel_launch(void* const* d_in, const int* in_sizes, int n_in,
                              void* d_out, int out_size)
{
    const float* data   = (const float*)d_in[0];
    const float* conv_w = (const float*)d_in[1];
    const float* conv_b = (const float*)d_in[2];
    float* out = (float*)d_out;

    conv_sigmoid_partial<<<NB, 256>>>(data, conv_w, conv_b);
    finalize_kernel<<<1, 256>>>(data, out);
}